// round 5
// baseline (speedup 1.0000x reference)
#include <cuda_runtime.h>

// out[i] = 2 * in[i], N = 100 floats (25 float4). Launch-latency-bound:
// 800 B of traffic vs ~3.2 us fixed launch overhead. Minimal SASS body:
// IMAD(addr) -> LDG.128 -> 4x FADD -> STG.128 -> EXIT.
// - 25 threads: HW lane-masks the partial warp, no guard predicate.
// - v+v == 2*v bit-exactly in fp32.
// - st.global.cs: streaming store, skip L2-allocate bookkeeping.
// - load default-cached: input stays L2-resident across graph replays.
__global__ void __launch_bounds__(32, 1) mul2_kernel(const float4* __restrict__ in,
                                                     float4* __restrict__ out) {
    int i = threadIdx.x;           // 0..24
    float4 v = __ldg(&in[i]);
    v.x += v.x; v.y += v.y; v.z += v.z; v.w += v.w;
    asm volatile("st.global.cs.v4.f32 [%0], {%1, %2, %3, %4};"
                 :: "l"(&out[i]), "f"(v.x), "f"(v.y), "f"(v.z), "f"(v.w)
                 : "memory");
}

extern "C" void kernel_launch(void* const* d_in, const int* in_sizes, int n_in,
                              void* d_out, int out_size) {
    const float4* in = (const float4*)d_in[0];
    float4* out = (float4*)d_out;
    mul2_kernel<<<1, 25>>>(in, out);
}